// round 1
// baseline (speedup 1.0000x reference)
#include <cuda_runtime.h>
#include <cstdint>

#define NBOX 8192
#define M 64
#define D_IN 2376
#define H 1024
#define NCLS 150
#define IOU_T 0.01f

// -------- persistent device scratch (allocation-free rule) --------
__device__ int   g_sel[M];
__device__ float g_x[M * D_IN];
__device__ float g_h1[M * H];
__device__ float g_h2[M * H];
__device__ float g_part[32 * M * H];   // split-K partials, pitch H, max 32 slices

// ============================================================
// Kernel 1: sort (bitonic, in-smem) + greedy NMS with early exit
// Single block, 1024 threads. Warp 0 does the sequential NMS.
// smem layout (dynamic):
//   sk    : u64[8192]  keys          [0, 65536)
//   cb    : float4[1024] cand boxes  [65536, 81920)
//   cord  : int[1024] cand orig idx  [81920, 86016)
//   s_sel : int[64]                  [86016, 86272)
//   s_supp: int[64]                  [86272, 86528)
//   st    : int[4]                   [86528, 86544)
// ============================================================
#define SORT_SMEM 86544

__device__ __forceinline__ bool iou_gt(float4 k, float ka, float4 c, float ca) {
    float ix1 = fmaxf(k.x, c.x), iy1 = fmaxf(k.y, c.y);
    float ix2 = fminf(k.z, c.z), iy2 = fminf(k.w, c.w);
    float iw = fmaxf(ix2 - ix1, 0.f), ih = fmaxf(iy2 - iy1, 0.f);
    float inter = iw * ih;
    return inter > IOU_T * (ka + ca - inter + 1e-9f);
}

__global__ void __launch_bounds__(1024) sortnms_kernel(
    const float* __restrict__ scores, const float* __restrict__ boxes,
    const int* __restrict__ labels, float* __restrict__ d_out, int out_size)
{
    extern __shared__ unsigned char smraw[];
    unsigned long long* sk = (unsigned long long*)smraw;
    float4* cb   = (float4*)(smraw + 65536);
    int*    cord = (int*)  (smraw + 81920);
    int*    s_sel  = (int*)(smraw + 86016);
    int*    s_supp = (int*)(smraw + 86272);
    int*    st     = (int*)(smraw + 86528);

    const int tid = threadIdx.x;
    const float4* boxes4 = (const float4*)boxes;

    // ---- build keys: descending score, ascending original index on ties ----
    for (int t = tid; t < NBOX; t += 1024) {
        unsigned int bits = __float_as_uint(scores[t]);
        unsigned long long key =
            ((unsigned long long)bits << 32) | (unsigned int)(NBOX - 1 - t);
        sk[t] = ~key;   // sort ascending on ~key == descending on key
    }

    // ---- bitonic sort ascending on sk ----
    for (int size = 2; size <= NBOX; size <<= 1) {
        for (int stride = size >> 1; stride > 0; stride >>= 1) {
            __syncthreads();
            #pragma unroll 4
            for (int t = tid; t < NBOX / 2; t += 1024) {
                int i = ((t & ~(stride - 1)) << 1) | (t & (stride - 1));
                int j = i | stride;
                bool up = ((i & size) == 0);
                unsigned long long a = sk[i], b = sk[j];
                if ((a > b) == up) { sk[i] = b; sk[j] = a; }
            }
        }
    }
    __syncthreads();

    // ---- greedy NMS, warp 0 sequential, chunked candidate staging ----
    float4 kb0 = make_float4(0, 0, 0, 0), kb1 = make_float4(0, 0, 0, 0);
    float ka0 = 0.f, ka1 = 0.f;
    int kept = 0, supp = 0;

    for (int c0 = 0; c0 < NBOX; c0 += 1024) {
        // all 1024 threads stage one candidate each
        {
            unsigned long long inv = ~sk[c0 + tid];
            int oi = NBOX - 1 - (int)(inv & 0xffffffffu);
            cord[tid] = oi;
            cb[tid] = boxes4[oi];
        }
        __syncthreads();

        if (tid < 32) {
            #pragma unroll 1
            for (int ii = 0; ii < 1024; ++ii) {
                float4 c = cb[ii];
                float ca = (c.z - c.x) * (c.w - c.y);
                bool sup = false;
                if (tid < kept)        sup  = iou_gt(kb0, ka0, c, ca);
                if (tid + 32 < kept)   sup |= iou_gt(kb1, ka1, c, ca);
                unsigned m = __ballot_sync(0xffffffffu, sup);
                if (m == 0) {
                    int slot = kept;
                    if (slot < 32) { if (tid == slot)      { kb0 = c; ka0 = ca; } }
                    else           { if (tid == slot - 32) { kb1 = c; ka1 = ca; } }
                    if (tid == 0) s_sel[slot] = cord[ii];
                    kept++;
                    if (kept == 64) break;
                } else {
                    if (supp < 64) {
                        if (tid == 0) s_supp[supp] = cord[ii];
                        supp++;
                    }
                }
            }
            if (tid == 0) { st[0] = kept; st[1] = supp; }
        }
        __syncthreads();
        if (st[0] >= 64) break;
    }

    // ---- fill (if <64 kept, earliest suppressed sorted positions) + outputs ----
    __syncthreads();
    int keptF = st[0];
    if (tid < 64) {
        int oi = (tid < keptF) ? s_sel[tid] : s_supp[tid - keptF];
        g_sel[tid] = oi;
        if (9600 + tid < out_size) d_out[9600 + tid] = (float)labels[oi];
        if (9664 + tid < out_size) d_out[9664 + tid] = scores[oi];
    }
}

// ============================================================
// Kernel 2: gather features/embed + pos-feature pipeline -> g_x[64][2376]
// grid 64 blocks x 256 threads
// ============================================================
__global__ void __launch_bounds__(256) gather_kernel(
    const float* __restrict__ boxes, const int* __restrict__ labels,
    const float* __restrict__ features, const float* __restrict__ embed_w,
    const float* __restrict__ bn_pos, const float* __restrict__ pos_w,
    const float* __restrict__ pos_b)
{
    const int b = blockIdx.x, tid = threadIdx.x;
    const int oi = g_sel[b];

    // features: 2048 floats = 512 float4
    const float4* src = (const float4*)(features + (size_t)oi * 2048);
    float4* dst = (float4*)(g_x + b * D_IN);
    #pragma unroll
    for (int i = tid; i < 512; i += 256) dst[i] = src[i];

    // embed: 200 floats
    const int lab = labels[oi] - 1;
    for (int i = tid; i < 200; i += 256)
        g_x[b * D_IN + 2048 + i] = embed_w[lab * 200 + i];

    // pos: center_size -> bn -> @pos_w + pos_b -> relu   (128 outputs)
    if (tid < 128) {
        float x1 = boxes[oi * 4 + 0], y1 = boxes[oi * 4 + 1];
        float x2 = boxes[oi * 4 + 2], y2 = boxes[oi * 4 + 3];
        float w = x2 - x1 + 1.f, h = y2 - y1 + 1.f;
        float cs[4] = { x1 + 0.5f * w, y1 + 0.5f * h, w, h };
        float acc = pos_b[tid];
        #pragma unroll
        for (int i = 0; i < 4; ++i) {
            float g = bn_pos[i], be = bn_pos[4 + i];
            float mn = bn_pos[8 + i], vr = bn_pos[12 + i];
            float v = (cs[i] - mn) * rsqrtf(vr + 1e-5f) * g + be;
            acc += v * pos_w[i * 128 + tid];
        }
        g_x[b * D_IN + 2248 + tid] = fmaxf(acc, 0.f);
    }
}

// ============================================================
// Kernel 3: split-K GEMM partial: block = 64 rows x 64 cols x one K-slice
// 256 threads, thread tile 4x4. Writes g_part[slice][row*1024 + col].
// asel: 0 -> g_x (lda 2376), 1 -> g_h1, 2 -> g_h2 (lda 1024)
// ============================================================
template<int FULLN>
__global__ void __launch_bounds__(256) gemm_part_kernel(
    int asel, const float* __restrict__ Wm, int lda, int N, int K, int kps)
{
    const float* __restrict__ A = (asel == 0) ? g_x : ((asel == 1) ? g_h1 : g_h2);
    __shared__ float As[32][65];

    const int tid  = threadIdx.x;
    const int col0 = blockIdx.x * 64 + (tid & 15) * 4;
    const int row0 = (tid >> 4) * 4;
    const int k0 = blockIdx.y * kps;
    const int k1 = min(k0 + kps, K);

    float acc[4][4];
    #pragma unroll
    for (int r = 0; r < 4; ++r)
        #pragma unroll
        for (int q = 0; q < 4; ++q) acc[r][q] = 0.f;

    for (int kb = k0; kb < k1; kb += 32) {
        const int kbn = min(32, k1 - kb);
        __syncthreads();
        #pragma unroll
        for (int idx = tid; idx < 64 * 32; idx += 256) {
            int kk = idx & 31, r = idx >> 5;
            As[kk][r] = (kk < kbn) ? A[r * lda + kb + kk] : 0.f;
        }
        __syncthreads();

        #pragma unroll 4
        for (int kk = 0; kk < kbn; ++kk) {
            float w0, w1, w2, w3;
            if (FULLN) {
                const float4 wv = *reinterpret_cast<const float4*>(
                    &Wm[(size_t)(kb + kk) * N + col0]);
                w0 = wv.x; w1 = wv.y; w2 = wv.z; w3 = wv.w;
            } else {
                const float* wp = &Wm[(size_t)(kb + kk) * N];
                w0 = (col0 + 0 < N) ? wp[col0 + 0] : 0.f;
                w1 = (col0 + 1 < N) ? wp[col0 + 1] : 0.f;
                w2 = (col0 + 2 < N) ? wp[col0 + 2] : 0.f;
                w3 = (col0 + 3 < N) ? wp[col0 + 3] : 0.f;
            }
            float a0 = As[kk][row0 + 0], a1 = As[kk][row0 + 1];
            float a2 = As[kk][row0 + 2], a3 = As[kk][row0 + 3];
            acc[0][0] += a0 * w0; acc[0][1] += a0 * w1; acc[0][2] += a0 * w2; acc[0][3] += a0 * w3;
            acc[1][0] += a1 * w0; acc[1][1] += a1 * w1; acc[1][2] += a1 * w2; acc[1][3] += a1 * w3;
            acc[2][0] += a2 * w0; acc[2][1] += a2 * w1; acc[2][2] += a2 * w2; acc[2][3] += a2 * w3;
            acc[3][0] += a3 * w0; acc[3][1] += a3 * w1; acc[3][2] += a3 * w2; acc[3][3] += a3 * w3;
        }
    }

    float* p = g_part + (size_t)blockIdx.y * (M * H);
    #pragma unroll
    for (int r = 0; r < 4; ++r) {
        if (FULLN) {
            *reinterpret_cast<float4*>(&p[(row0 + r) * H + col0]) =
                make_float4(acc[r][0], acc[r][1], acc[r][2], acc[r][3]);
        } else {
            #pragma unroll
            for (int q = 0; q < 4; ++q)
                if (col0 + q < N) p[(row0 + r) * H + col0 + q] = acc[r][q];
        }
    }
}

// ============================================================
// Kernel 4: epilogue — sum S partials, +bias, optional BN+ReLU, write dest
// outsel: 1 -> g_h1, 2 -> g_h2, 3 -> d_out (ldo = N)
// bn layout: [gamma(N), beta(N), mean(N), var(N)]
// ============================================================
__global__ void __launch_bounds__(256) epilogue_kernel(
    int S, const float* __restrict__ bias, const float* __restrict__ bn,
    int N, int outsel, float* __restrict__ dout, int bnrelu)
{
    const int idx = blockIdx.x * 256 + threadIdx.x;
    if (idx >= M * N) return;
    const int r = idx / N, c = idx - r * N;

    float s = 0.f;
    for (int i = 0; i < S; ++i) s += g_part[i * (M * H) + r * H + c];
    s += bias[c];
    if (bnrelu) {
        s = (s - bn[2 * N + c]) * rsqrtf(bn[3 * N + c] + 1e-5f) * bn[c] + bn[N + c];
        s = fmaxf(s, 0.f);
    }
    float* out = (outsel == 1) ? g_h1 : ((outsel == 2) ? g_h2 : dout);
    const int ldo = (outsel == 3) ? N : H;
    out[r * ldo + c] = s;
}

// ============================================================
extern "C" void kernel_launch(void* const* d_in, const int* in_sizes, int n_in,
                              void* d_out_v, int out_size)
{
    const float* boxes    = (const float*)d_in[0];
    const float* scores   = (const float*)d_in[1];
    const int*   labels   = (const int*)  d_in[2];
    const float* features = (const float*)d_in[3];
    const float* embed_w  = (const float*)d_in[4];
    const float* bn_pos   = (const float*)d_in[5];
    const float* pos_w    = (const float*)d_in[6];
    const float* pos_b    = (const float*)d_in[7];
    const float* lin1_w   = (const float*)d_in[8];
    const float* lin1_b   = (const float*)d_in[9];
    const float* bn1      = (const float*)d_in[10];
    const float* lin2_w   = (const float*)d_in[11];
    const float* lin2_b   = (const float*)d_in[12];
    const float* bn2      = (const float*)d_in[13];
    const float* lin3_w   = (const float*)d_in[14];
    const float* lin3_b   = (const float*)d_in[15];
    const float* bn3      = (const float*)d_in[16];
    const float* lin4_w   = (const float*)d_in[17];
    const float* lin4_b   = (const float*)d_in[18];
    float* d_out = (float*)d_out_v;

    cudaFuncSetAttribute(sortnms_kernel,
                         cudaFuncAttributeMaxDynamicSharedMemorySize, SORT_SMEM);

    // sort + NMS + select (also writes labels/scores to d_out tail)
    sortnms_kernel<<<1, 1024, SORT_SMEM>>>(scores, boxes, labels, d_out, out_size);

    // build x[64][2376]
    gather_kernel<<<64, 256>>>(boxes, labels, features, embed_w, bn_pos, pos_w, pos_b);

    // layer 1: [64,2376] @ [2376,1024], S=12 (12*198 = 2376)
    gemm_part_kernel<1><<<dim3(16, 12), 256>>>(0, lin1_w, D_IN, H, D_IN, 198);
    epilogue_kernel<<<(M * H + 255) / 256, 256>>>(12, lin1_b, bn1, H, 1, d_out, 1);

    // layer 2: [64,1024] @ [1024,1024], S=9 (kps 114)
    gemm_part_kernel<1><<<dim3(16, 9), 256>>>(1, lin2_w, H, H, H, 114);
    epilogue_kernel<<<(M * H + 255) / 256, 256>>>(9, lin2_b, bn2, H, 2, d_out, 1);

    // layer 3
    gemm_part_kernel<1><<<dim3(16, 9), 256>>>(2, lin3_w, H, H, H, 114);
    epilogue_kernel<<<(M * H + 255) / 256, 256>>>(9, lin3_b, bn3, H, 1, d_out, 1);

    // layer 4: [64,1024] @ [1024,150], S=32 (kps 32), no bn/relu, to d_out
    gemm_part_kernel<0><<<dim3(3, 32), 256>>>(1, lin4_w, H, NCLS, H, 32);
    epilogue_kernel<<<(M * NCLS + 255) / 256, 256>>>(32, lin4_b, bn1, NCLS, 3, d_out, 0);
}